// round 16
// baseline (speedup 1.0000x reference)
#include <cuda_runtime.h>
#include <cuda_fp16.h>
#include <math.h>
#include <stdint.h>
#include <string.h>

#define B2   32
#define T    512
#define DD   512
#define H    8
#define DH   64
#define TE   2048
#define NTOK (B2*T)               /* 16384 */
#define NELEM ((size_t)NTOK*DD)   /* 8388608 */
#define LOG2E 1.4426950408889634f

// ---------------- fp32 scratch ----------------
#define OFF_Y  ((size_t)0)        // [b,n,D]
#define OFF_SS (OFF_Y + NELEM)                      // [32][1024] FiLM params
#define OFF_EP (OFF_SS + (size_t)B2*2*DD)           // [64][32][1024] split-K partials
#define SCRATCH_TOTAL (OFF_EP + (size_t)64*B2*2*DD)

__device__ __align__(16) float g_scratch[SCRATCH_TOTAL];
// fp16 operands
__device__ __align__(16) __half g_xn[NELEM];
__device__ __align__(16) __half g_tn[NELEM];
__device__ __align__(16) __half g_hs[NELEM];
__device__ __align__(16) __half g_qh[NELEM];   // head layout [b,h,n,dh], pre-scaled by 1/8
__device__ __align__(16) __half g_kh[NELEM];
__device__ __align__(16) __half g_vh[NELEM];
__device__ __align__(16) __half g_wt[4 * (size_t)DD * DD];   // transposed weights [n][k]
__device__ __align__(16) __half g_mb[(size_t)B2*T*T];        // mask bias, log2 domain

// ---------------- helpers ----------------
__device__ __forceinline__ uint32_t h2_u32(__half2 h) {
    uint32_t u;
    memcpy(&u, &h, 4);
    return u;
}

// fp16 m16n8k16
__device__ __forceinline__ void mma16(float* c, const uint32_t* a, const uint32_t* b) {
    asm volatile(
        "mma.sync.aligned.m16n8k16.row.col.f32.f16.f16.f32 "
        "{%0,%1,%2,%3},{%4,%5,%6,%7},{%8,%9},{%0,%1,%2,%3};\n"
        : "+f"(c[0]), "+f"(c[1]), "+f"(c[2]), "+f"(c[3])
        : "r"(a[0]), "r"(a[1]), "r"(a[2]), "r"(a[3]), "r"(b[0]), "r"(b[1]));
}

// ldmatrix x4 (b16), non-transposed and transposed
__device__ __forceinline__ void ldsm4(uint32_t& r0, uint32_t& r1, uint32_t& r2, uint32_t& r3,
                                      uint32_t addr) {
    asm volatile("ldmatrix.sync.aligned.m8n8.x4.shared.b16 {%0,%1,%2,%3}, [%4];"
                 : "=r"(r0), "=r"(r1), "=r"(r2), "=r"(r3) : "r"(addr));
}
__device__ __forceinline__ void ldsm4t(uint32_t& r0, uint32_t& r1, uint32_t& r2, uint32_t& r3,
                                       uint32_t addr) {
    asm volatile("ldmatrix.sync.aligned.m8n8.x4.trans.shared.b16 {%0,%1,%2,%3}, [%4];"
                 : "=r"(r0), "=r"(r1), "=r"(r2), "=r"(r3) : "r"(addr));
}

__device__ __forceinline__ uint32_t smem_u32(const void* p) {
    uint32_t a;
    asm("{ .reg .u64 t; cvta.to.shared.u64 t, %1; cvt.u32.u64 %0, t; }" : "=r"(a) : "l"(p));
    return a;
}
__device__ __forceinline__ void cp16(uint32_t d, const void* s) {
    asm volatile("cp.async.cg.shared.global [%0], [%1], 16;\n" :: "r"(d), "l"(s));
}
__device__ __forceinline__ void cp_commit() {
    asm volatile("cp.async.commit_group;\n" ::: "memory");
}
__device__ __forceinline__ void cp_wait1() {
    asm volatile("cp.async.wait_group 1;\n" ::: "memory");
}
__device__ __forceinline__ void cp_wait0() {
    asm volatile("cp.async.wait_group 0;\n" ::: "memory");
}

// ================= mask -> fp16 log2-domain bias =================
__global__ void mprep_kernel(const float* __restrict__ mask) {
    size_t i = ((size_t)blockIdx.x * 256 + threadIdx.x) * 4;
    float4 m = *(const float4*)(mask + i);
    float v0 = fmaxf((1.0f - m.x) * (-100000.0f) * LOG2E, -60000.0f);
    float v1 = fmaxf((1.0f - m.y) * (-100000.0f) * LOG2E, -60000.0f);
    float v2 = fmaxf((1.0f - m.z) * (-100000.0f) * LOG2E, -60000.0f);
    float v3 = fmaxf((1.0f - m.w) * (-100000.0f) * LOG2E, -60000.0f);
    __half2* d = (__half2*)(g_mb + i);
    d[0] = __floats2half2_rn(v0, v1);
    d[1] = __floats2half2_rn(v2, v3);
}

// ================= 4-in-1 weight transpose + fp16 convert =================
__global__ void wtrans4_kernel(const float* __restrict__ W0, const float* __restrict__ W1,
                               const float* __restrict__ W2, const float* __restrict__ W3) {
    __shared__ float t[32][33];
    int wi = blockIdx.z;
    const float* W = (wi == 0) ? W0 : (wi == 1) ? W1 : (wi == 2) ? W2 : W3;
    __half* Wt = g_wt + (size_t)wi * DD * DD;
    int nb = blockIdx.x * 32, kb = blockIdx.y * 32;
    int tx = threadIdx.x, ty = threadIdx.y;   // 32 x 8
    #pragma unroll
    for (int i = ty; i < 32; i += 8)
        t[i][tx] = W[(size_t)(kb + i) * DD + nb + tx];
    __syncthreads();
    #pragma unroll
    for (int i = ty; i < 32; i += 8)
        Wt[(size_t)(nb + i) * DD + kb + tx] = __float2half_rn(t[tx][i]);
}

// ================= fused LayerNorm -> fp16 (xn from xa, tn from xb) =================
__global__ void ln2_kernel(const float* __restrict__ x1, const float* __restrict__ x2,
                           const float* __restrict__ gx, const float* __restrict__ bx,
                           const float* __restrict__ gt, const float* __restrict__ bt) {
    int r = blockIdx.x;                // 0..NTOK/2-1
    int tid = threadIdx.x;             // 128 threads, 4 floats each
    float4 v1 = ((const float4*)(x1 + (size_t)r*DD))[tid];
    float4 v2 = ((const float4*)(x2 + (size_t)r*DD))[tid];

    float s1 = v1.x+v1.y+v1.z+v1.w, q1 = v1.x*v1.x+v1.y*v1.y+v1.z*v1.z+v1.w*v1.w;
    float s2 = v2.x+v2.y+v2.z+v2.w, q2 = v2.x*v2.x+v2.y*v2.y+v2.z*v2.z+v2.w*v2.w;

    __shared__ float red[4][4];
    #pragma unroll
    for (int o = 16; o; o >>= 1) {
        s1 += __shfl_xor_sync(0xffffffffu, s1, o);
        q1 += __shfl_xor_sync(0xffffffffu, q1, o);
        s2 += __shfl_xor_sync(0xffffffffu, s2, o);
        q2 += __shfl_xor_sync(0xffffffffu, q2, o);
    }
    if ((tid & 31) == 0) {
        int w = tid >> 5;
        red[0][w] = s1; red[1][w] = q1; red[2][w] = s2; red[3][w] = q2;
    }
    __syncthreads();
    s1 = red[0][0]+red[0][1]+red[0][2]+red[0][3];
    q1 = red[1][0]+red[1][1]+red[1][2]+red[1][3];
    s2 = red[2][0]+red[2][1]+red[2][2]+red[2][3];
    q2 = red[3][0]+red[3][1]+red[3][2]+red[3][3];
    float m1 = s1*(1.0f/DD), iv1 = rsqrtf(q1*(1.0f/DD) - m1*m1 + 1e-5f);
    float m2 = s2*(1.0f/DD), iv2 = rsqrtf(q2*(1.0f/DD) - m2*m2 + 1e-5f);

    float4 ggx = ((const float4*)gx)[tid], bbx = ((const float4*)bx)[tid];
    float4 ggt = ((const float4*)gt)[tid], bbt = ((const float4*)bt)[tid];

    float n1[4] = {(v1.x-m1)*iv1, (v1.y-m1)*iv1, (v1.z-m1)*iv1, (v1.w-m1)*iv1};
    float n2[4] = {(v2.x-m2)*iv2, (v2.y-m2)*iv2, (v2.z-m2)*iv2, (v2.w-m2)*iv2};
    const float* gxp = &ggx.x; const float* bxp = &bbx.x;
    const float* gtp = &ggt.x; const float* btp = &bbt.x;

    const int half_tok = NTOK/2;

    #pragma unroll
    for (int variant = 0; variant < 4; variant++) {
        const float* nv = (variant == 0 || variant == 3) ? n1 : n2;
        const float* gp = (variant < 2) ? gxp : gtp;
        const float* bp = (variant < 2) ? bxp : btp;
        __half* base = (variant < 2) ? g_xn : g_tn;
        int row = (variant == 0 || variant == 2) ? r : r + half_tok;
        float o0 = nv[0]*gp[0] + bp[0];
        float o1 = nv[1]*gp[1] + bp[1];
        float o2 = nv[2]*gp[2] + bp[2];
        float o3 = nv[3]*gp[3] + bp[3];
        __half2* d2 = (__half2*)(base + (size_t)row*DD);
        d2[2*tid]   = __floats2half2_rn(o0, o1);
        d2[2*tid+1] = __floats2half2_rn(o2, o3);
    }
}

// ================= 3-stage pipelined fp16 MMA GEMM =================
#define HROW 40            /* halves per smem row */
#define WROW 20            /* words per smem row */
#define STG_H (128*HROW)   /* halves per stage: 5120 */
template<bool QKV>
__global__ void __launch_bounds__(256)
mma_gemm(const float* __restrict__ b0p, const float* __restrict__ b1p,
         const float* __restrict__ b2p,
         const float* __restrict__ x1, const float* __restrict__ x2,
         float* __restrict__ outp) {
    extern __shared__ __half hsm[];
    __half* As = hsm;                 // 3 stages x 5120 halves
    __half* Bs = hsm + 3*STG_H;
    uint32_t a_base = smem_u32(As), b_base = smem_u32(Bs);

    int n0g = blockIdx.x * 128;
    int widx, n0;
    const __half *A, *Wt;
    const float* bias;
    __half* Ch = nullptr;
    if (QKV) {
        widx = n0g >> 9;
        n0 = n0g & 511;
        A = (widx == 0) ? g_xn : g_tn;
        Wt = g_wt + (size_t)widx * DD * DD + (size_t)n0 * DD;
        bias = (widx == 0) ? b0p : (widx == 1) ? b1p : b2p;
        Ch = (widx == 0) ? g_qh : (widx == 1) ? g_kh : g_vh;
    } else {
        widx = 3;
        n0 = n0g;
        A = g_hs;
        Wt = g_wt + (size_t)3 * DD * DD + (size_t)n0 * DD;
        bias = b0p;
    }

    int tid = threadIdx.x, lane = tid & 31, wid = tid >> 5;
    int wm = wid >> 2, wn = wid & 3;
    int gid = lane >> 2, tig = lane & 3;
    int m0 = blockIdx.y * 128;
    float c[4][4][4] = {};

    int lrow = tid >> 1;            // 0..127
    int lch  = (tid & 1) * 2;       // chunk 0/1 or 2/3 (8 halves each)

    // prologue: stages 0, 1
    #pragma unroll
    for (int s = 0; s < 2; s++) {
        int so = s * STG_H, k0 = s * 32;
        #pragma unroll
        for (int cc = 0; cc < 2; cc++) {
            int ch = lch + cc;
            cp16(a_base + (uint32_t)(so + lrow*HROW + ch*8)*2, A  + (size_t)(m0+lrow)*DD + k0 + ch*8);
            cp16(b_base + (uint32_t)(so + lrow*HROW + ch*8)*2, Wt + (size_t)lrow*DD      + k0 + ch*8);
        }
        cp_commit();
    }

    for (int it = 0; it < 16; it++) {
        cp_wait1();
        __syncthreads();

        if (it + 2 < 16) {
            int so = ((it + 2) % 3) * STG_H;
            int k0 = (it + 2) * 32;
            #pragma unroll
            for (int cc = 0; cc < 2; cc++) {
                int ch = lch + cc;
                cp16(a_base + (uint32_t)(so + lrow*HROW + ch*8)*2, A  + (size_t)(m0+lrow)*DD + k0 + ch*8);
                cp16(b_base + (uint32_t)(so + lrow*HROW + ch*8)*2, Wt + (size_t)lrow*DD      + k0 + ch*8);
            }
        }
        cp_commit();

        int stw = (it % 3) * (STG_H/2);     // stage offset in words
        const uint32_t* Au = (const uint32_t*)As + stw;
        const uint32_t* Bu = (const uint32_t*)Bs + stw;
        #pragma unroll
        for (int ks = 0; ks < 2; ks++) {
            int c0w = ks*8 + tig;
            int c1w = c0w + 4;
            uint32_t a[4][4];
            #pragma unroll
            for (int mi = 0; mi < 4; mi++) {
                int rm = (wm*64 + mi*16 + gid) * WROW;
                a[mi][0] = Au[rm + c0w];
                a[mi][1] = Au[rm + 8*WROW + c0w];
                a[mi][2] = Au[rm + c1w];
                a[mi][3] = Au[rm + 8*WROW + c1w];
            }
            uint32_t b[4][2];
            #pragma unroll
            for (int ni = 0; ni < 4; ni++) {
                int rn = (wn*32 + ni*8 + gid) * WROW;
                b[ni][0] = Bu[rn + c0w];
                b[ni][1] = Bu[rn + c1w];
            }
            #pragma unroll
            for (int mi = 0; mi < 4; mi++)
                #pragma unroll
                for (int ni = 0; ni < 4; ni++)
                    mma16(c[mi][ni], a[mi], b[ni]);
        }
    }

    float qscale = (QKV && widx == 0) ? 0.125f : 1.0f;
    #pragma unroll
    for (int mi = 0; mi < 4; mi++) {
        #pragma unroll
        for (int ni = 0; ni < 4; ni++) {
            #pragma unroll
            for (int r = 0; r < 4; r++) {
                int m = m0 + wm*64 + mi*16 + gid + ((r >= 2) ? 8 : 0);
                int n = n0 + wn*32 + ni*8 + 2*tig + (r & 1);
                float v = c[mi][ni][r] + bias[n];
                if (QKV) {
                    int b_ = m >> 9, nn = m & 511, h = n >> 6, d = n & 63;
                    Ch[(((size_t)(b_*H + h)*T + nn)*DH) + d] = __float2half_rn(v * qscale);
                } else {
                    const float* src = (m < NTOK/2) ? x1 + (size_t)m*DD
                                                    : x2 + (size_t)(m - NTOK/2)*DD;
                    outp[(size_t)m*DD + n] = v + src[n];
                }
            }
        }
    }
}

// ================= fused flash attention (exp2 domain, fp16 mask bias) =================
// Q pre-scaled by 1/8; fragments in registers; K,V via ldmatrix; cp.async double buffer.
// Block = 64 q-rows of one (b,h). 4 warps x 16 rows.
// smem (halves, rows padded to 72): 2 x (sK + sV) = 36,864 bytes
#define FHROW 72
__global__ void __launch_bounds__(128)
fa_kernel() {
    extern __shared__ __half fsm[];
    __half* sKb[2] = {fsm,              fsm + 2*64*FHROW};
    __half* sVb[2] = {fsm + 64*FHROW,   fsm + 3*64*FHROW};

    int bh = blockIdx.y, b = bh >> 3, h = bh & 7;
    int n0 = blockIdx.x * 64;
    const __half* Q = g_qh + (size_t)bh*T*DH;
    const __half* K = g_kh + (size_t)bh*T*DH;
    const __half* V = g_vh + (size_t)bh*T*DH;

    int tid = threadIdx.x, lane = tid & 31, w = tid >> 5;
    int gid = lane >> 2, tig = lane & 3;
    int w16 = w * 16;
    int rA = w16 + gid, rB = rA + 8;

    const __half* mrowA = g_mb + ((size_t)b*T + n0 + rA)*T;
    const __half* mrowB = g_mb + ((size_t)b*T + n0 + rB)*T;

    // each thread owns one 32-half half-row: row = tid>>1, halves lh..lh+31
    int lrow = tid >> 1, lh = (tid & 1) * 32;

    // ldmatrix lane addressing
    int lg = lane >> 3, lr8 = lane & 7;
    uint32_t vlane_off = (uint32_t)(((lg & 1)*8 + lr8) * FHROW + (lg >> 1) * 8) * 2;
    uint32_t klane_off = (uint32_t)(((lg >> 1)*8 + lr8) * FHROW + (lg & 1) * 8) * 2;

    // Q fragments straight from global into registers (one-time)
    uint32_t aq[4][4];
    #pragma unroll
    for (int ks = 0; ks < 4; ks++) {
        int k0 = ks*16 + 2*tig;
        aq[ks][0] = *(const uint32_t*)(Q + (size_t)(n0+rA)*DH + k0);
        aq[ks][1] = *(const uint32_t*)(Q + (size_t)(n0+rB)*DH + k0);
        aq[ks][2] = *(const uint32_t*)(Q + (size_t)(n0+rA)*DH + k0 + 8);
        aq[ks][3] = *(const uint32_t*)(Q + (size_t)(n0+rB)*DH + k0 + 8);
    }

    // prefetch K/V tile 0 into buffer 0
    {
        uint32_t kb = smem_u32(sKb[0]), vb = smem_u32(sVb[0]);
        #pragma unroll
        for (int j = 0; j < 4; j++) {
            uint32_t so = (uint32_t)(lrow*FHROW + lh + j*8)*2;
            cp16(kb + so, K + (size_t)lrow*DH + lh + j*8);
            cp16(vb + so, V + (size_t)lrow*DH + lh + j*8);
        }
        cp_commit();
    }

    float co[8][4] = {};
    float miA = -1e30f, miB = -1e30f;
    float lA = 0.0f, lB = 0.0f;

    for (int mt = 0; mt < T/64; mt++) {
        int bi = mt & 1;
        cp_wait0();
        __syncthreads();

        if (mt + 1 < T/64) {
            int m1 = (mt + 1) * 64;
            uint32_t kb = smem_u32(sKb[bi ^ 1]), vb = smem_u32(sVb[bi ^ 1]);
            #pragma unroll
            for (int j = 0; j < 4; j++) {
                uint32_t so = (uint32_t)(lrow*FHROW + lh + j*8)*2;
                cp16(kb + so, K + (size_t)(m1+lrow)*DH + lh + j*8);
                cp16(vb + so, V + (size_t)(m1+lrow)*DH + lh + j*8);
            }
            cp_commit();
        }

        int m0 = mt * 64;
        uint32_t kbase = smem_u32(sKb[bi]);
        uint32_t vbase = smem_u32(sVb[bi]);

        // S = Q @ K^T ; K fragments via ldmatrix.x4
        float cs[8][4] = {};
        #pragma unroll
        for (int ks = 0; ks < 4; ks++) {
            uint32_t kcol = kbase + (uint32_t)(ks*16)*2 + klane_off;
            #pragma unroll
            for (int nip = 0; nip < 4; nip++) {
                uint32_t addr = kcol + (uint32_t)(nip*16*FHROW)*2;
                uint32_t b0, b1, b2, b3;
                ldsm4(b0, b1, b2, b3, addr);
                uint32_t bb0[2] = {b0, b1};
                uint32_t bb1[2] = {b2, b3};
                mma16(cs[2*nip],   aq[ks], bb0);
                mma16(cs[2*nip+1], aq[ks], bb1);
            }
        }

        // log2-domain scores: cs2 = cs*log2e + mb ; row max
        float rmA = -1e30f, rmB = -1e30f;
        #pragma unroll
        for (int ni = 0; ni < 8; ni++) {
            int col = ni*8 + 2*tig;
            float2 mA = __half22float2(*(const __half2*)(mrowA + m0 + col));
            float2 mB = __half22float2(*(const __half2*)(mrowB + m0 + col));
            cs[ni][0] = cs[ni][0]*LOG2E + mA.x;
            cs[ni][1] = cs[ni][1]*LOG2E + mA.y;
            cs[ni][2] = cs[ni][2]*LOG2E + mB.x;
            cs[ni][3] = cs[ni][3]*LOG2E + mB.y;
            rmA = fmaxf(rmA, fmaxf(cs[ni][0], cs[ni][1]));
            rmB = fmaxf(rmB, fmaxf(cs[ni][2], cs[ni][3]));
        }
        rmA = fmaxf(rmA, __shfl_xor_sync(0xffffffffu, rmA, 1));
        rmA = fmaxf(rmA, __shfl_xor_sync(0xffffffffu, rmA, 2));
        rmB = fmaxf(rmB, __shfl_xor_sync(0xffffffffu, rmB, 1));
        rmB = fmaxf(rmB, __shfl_xor_sync(0xffffffffu, rmB, 2));

        float mnA = fmaxf(miA, rmA), mnB = fmaxf(miB, rmB);
        float alA = exp2f(miA - mnA), alB = exp2f(miB - mnB);
        miA = mnA; miB = mnB;

        // exp2 -> P packed directly as fp16 A-fragments (register resident)
        uint32_t ph[8][2];
        float sumA = 0.0f, sumB = 0.0f;
        #pragma unroll
        for (int ni = 0; ni < 8; ni++) {
            float p0 = exp2f(cs[ni][0] - mnA);
            float p1 = exp2f(cs[ni][1] - mnA);
            float p2 = exp2f(cs[ni][2] - mnB);
            float p3 = exp2f(cs[ni][3] - mnB);
            sumA += p0 + p1; sumB += p2 + p3;
            ph[ni][0] = h2_u32(__floats2half2_rn(p0, p1));
            ph[ni][1] = h2_u32(__floats2half2_rn(p2, p3));
        }
        sumA += __shfl_xor_sync(0xffffffffu, sumA, 1);
        sumA += __shfl_xor_sync(0xffffffffu, sumA, 2);
        sumB += __shfl_xor_sync(0xffffffffu, sumB, 1);
        sumB += __shfl_xor_sync(0xffffffffu, sumB, 2);
        lA = lA * alA + sumA;
        lB = lB * alB + sumB;

        #pragma unroll
        for (int ni = 0; ni < 8; ni++) {
            co[ni][0] *= alA; co[ni][1] *= alA;
            co[ni][2] *= alB; co[ni][3] *= alB;
        }

        // O += P @ V   (A = ph regs; B = V via ldmatrix.x4.trans)
        #pragma unroll
        for (int ks = 0; ks < 4; ks++) {
            uint32_t a[4];
            a[0] = ph[2*ks][0];
            a[1] = ph[2*ks][1];
            a[2] = ph[2*ks+1][0];
            a[3] = ph[2*ks+1][1];
            uint32_t krow_off = vbase + (uint32_t)(ks*16*FHROW)*2 + vlane_off;
            #pragma unroll
            for (int nip = 0; nip < 4; nip++) {
                uint32_t addr = krow_off + (uint32_t)(nip*16)*2;
                uint32_t b0, b1, b2, b3;
                ldsm4t(b0, b1, b2, b3, addr);
                uint32_t bb0[2] = {b0, b1};
                uint32_t bb1[2] = {b2, b3};
                mma16(co[2*nip],   a, bb0);
                mma16(co[2*nip+1], a, bb1);
            }
        }
    }

    // epilogue: normalize + write Y[b,n,D] fp32
    float invA = 1.0f / lA, invB = 1.0f / lB;
    float* Y = g_scratch + OFF_Y;
    int nA = n0 + rA, nB = n0 + rB;
    #pragma unroll
    for (int ni = 0; ni < 8; ni++) {
        int dcol = h*DH + ni*8 + 2*tig;
        float2 oa; oa.x = co[ni][0]*invA; oa.y = co[ni][1]*invA;
        float2 ob; ob.x = co[ni][2]*invB; ob.y = co[ni][3]*invB;
        *(float2*)(Y + ((size_t)(b*T + nA))*DD + dcol) = oa;
        *(float2*)(Y + ((size_t)(b*T + nB))*DD + dcol) = ob;
    }
}

// ================= emb FiLM GEMM, split-K 64 phase 1 =================
__global__ void __launch_bounds__(256)
emb2_kernel(const float* __restrict__ emb, const float* __restrict__ Wemb) {
    __shared__ float se[32 * 33];
    int col0 = blockIdx.x * 64, k0 = blockIdx.y * 32;
    int tid = threadIdx.x;
    for (int i = tid; i < 32 * 32; i += 256) {
        int b = i >> 5, kk = i & 31;
        float e = emb[(size_t)b * TE + k0 + kk];
        se[b * 33 + kk] = e / (1.0f + __expf(-e));
    }
    __syncthreads();

    int col = col0 + (tid & 63);
    int bg = (tid >> 6) << 3;          // 0,8,16,24
    float acc[8] = {};
    #pragma unroll
    for (int kk = 0; kk < 32; kk++) {
        float wv = Wemb[(size_t)(k0 + kk) * (2 * DD) + col];
        #pragma unroll
        for (int j = 0; j < 8; j++)
            acc[j] += se[(bg + j) * 33 + kk] * wv;
    }
    float* P = g_scratch + OFF_EP + (size_t)blockIdx.y * (B2 * 2 * DD);
    #pragma unroll
    for (int j = 0; j < 8; j++)
        P[(size_t)(bg + j) * (2 * DD) + col] = acc[j];
}

// ================= emb split-K phase 2: reduce 64 partials + bias =================
__global__ void embred_kernel(const float* __restrict__ bemb) {
    int i = blockIdx.x * 256 + threadIdx.x;   // 0 .. 32*1024-1
    float s = bemb[i & (2 * DD - 1)];
    #pragma unroll 16
    for (int ks = 0; ks < 64; ks++)
        s += g_scratch[OFF_EP + (size_t)ks * (B2 * 2 * DD) + i];
    g_scratch[OFF_SS + i] = s;
}

// ================= hs = silu( LN(y)*(1+scale) + shift ) -> fp16 =================
__global__ void film_kernel(const float* __restrict__ sbg, const float* __restrict__ sbb) {
    int r = blockIdx.x;
    int b = r >> 9;
    const float* y = g_scratch + OFF_Y + (size_t)r*DD;
    __half* dst = g_hs + (size_t)r*DD;
    const float* ss = g_scratch + OFF_SS + (size_t)b*(2*DD);

    int tid = threadIdx.x;
    float4 v = ((const float4*)y)[tid];
    float s  = v.x + v.y + v.z + v.w;
    float sq = v.x*v.x + v.y*v.y + v.z*v.z + v.w*v.w;
    __shared__ float red[2][4];
    #pragma unroll
    for (int o = 16; o; o >>= 1) {
        s  += __shfl_xor_sync(0xffffffffu, s,  o);
        sq += __shfl_xor_sync(0xffffffffu, sq, o);
    }
    if ((tid & 31) == 0) { red[0][tid>>5] = s; red[1][tid>>5] = sq; }
    __syncthreads();
    s  = red[0][0] + red[0][1] + red[0][2] + red[0][3];
    sq = red[1][0] + red[1][1] + red[1][2] + red[1][3];
    float mean = s * (1.0f/DD);
    float var  = sq * (1.0f/DD) - mean*mean;
    float inv  = rsqrtf(var + 1e-5f);

    int col = tid * 4;
    float vv[4] = {v.x, v.y, v.z, v.w};
    float o[4];
    #pragma unroll
    for (int cc = 0; cc < 4; cc++) {
        float ln = (vv[cc] - mean) * inv * sbg[col + cc] + sbb[col + cc];
        float hh = ln * (1.0f + ss[col + cc]) + ss[512 + col + cc];
        o[cc] = hh / (1.0f + expf(-hh));
    }
    __half2* d2 = (__half2*)dst;
    d2[2*tid]   = __floats2half2_rn(o[0], o[1]);
    d2[2*tid+1] = __floats2half2_rn(o[2], o[3]);
}

// ================= launch =================
extern "C" void kernel_launch(void* const* d_in, const int* in_sizes, int n_in,
                              void* d_out, int out_size) {
    const float* x1    = (const float*)d_in[0];
    const float* x2    = (const float*)d_in[1];
    const float* emb   = (const float*)d_in[2];
    const float* mask  = (const float*)d_in[3];
    const float* ln_x_g = (const float*)d_in[4];
    const float* ln_x_b = (const float*)d_in[5];
    const float* ln_t_g = (const float*)d_in[6];
    const float* ln_t_b = (const float*)d_in[7];
    const float* Wq = (const float*)d_in[8];
    const float* bq = (const float*)d_in[9];
    const float* Wk = (const float*)d_in[10];
    const float* bk = (const float*)d_in[11];
    const float* Wv = (const float*)d_in[12];
    const float* bv = (const float*)d_in[13];
    const float* Wemb = (const float*)d_in[14];
    const float* bemb = (const float*)d_in[15];
    const float* sb_g = (const float*)d_in[16];
    const float* sb_b = (const float*)d_in[17];
    const float* Wout = (const float*)d_in[18];
    const float* bout = (const float*)d_in[19];
    float* out = (float*)d_out;

    const int gemm_smem = 6 * STG_H * 2;       // 61440 bytes
    const int fa_smem   = 4 * 64 * FHROW * 2;  // 36864 bytes
    cudaFuncSetAttribute(mma_gemm<true>,  cudaFuncAttributeMaxDynamicSharedMemorySize, gemm_smem);
    cudaFuncSetAttribute(mma_gemm<false>, cudaFuncAttributeMaxDynamicSharedMemorySize, gemm_smem);
    cudaFuncSetAttribute(fa_kernel,       cudaFuncAttributeMaxDynamicSharedMemorySize, fa_smem);

    wtrans4_kernel<<<dim3(16, 16, 4), dim3(32, 8)>>>(Wq, Wk, Wv, Wout);
    ln2_kernel<<<NTOK/2, 128>>>(x1, x2, ln_x_g, ln_x_b, ln_t_g, ln_t_b);
    mprep_kernel<<<(B2*T*T)/(256*4), 256>>>(mask);

    // fused Q/K/V projection: N = 1536 (slot 4 -> profiled by ncu this round)
    mma_gemm<true><<<dim3(12, NTOK/128), 256, gemm_smem>>>(bq, bk, bv, x1, x2, nullptr);

    fa_kernel<<<dim3(T/64, B2*H), 128, fa_smem>>>();

    // FiLM emb GEMM (split-K 64, two phases) — independent of attention
    emb2_kernel<<<dim3(16, 64), 256>>>(emb, Wemb);
    embred_kernel<<<(B2*2*DD)/256, 256>>>(bemb);

    film_kernel<<<NTOK, 128>>>(sb_g, sb_b);
    mma_gemm<false><<<dim3(4, NTOK/128), 256, gemm_smem>>>(bout, nullptr, nullptr, x1, x2, out);
}

// round 17
// speedup vs baseline: 1.0859x; 1.0859x over previous
#include <cuda_runtime.h>
#include <cuda_fp16.h>
#include <math.h>
#include <stdint.h>
#include <string.h>

#define B2   32
#define T    512
#define DD   512
#define H    8
#define DH   64
#define TE   2048
#define NTOK (B2*T)               /* 16384 */
#define NELEM ((size_t)NTOK*DD)   /* 8388608 */
#define LOG2E 1.4426950408889634f
#define MBIAS (-100000.0f * LOG2E)

// ---------------- fp32 scratch ----------------
#define OFF_Y  ((size_t)0)        // [b,n,D]
#define OFF_SS (OFF_Y + NELEM)                      // [32][1024] FiLM params
#define OFF_EP (OFF_SS + (size_t)B2*2*DD)           // [64][32][1024] split-K partials
#define SCRATCH_TOTAL (OFF_EP + (size_t)64*B2*2*DD)

__device__ __align__(16) float g_scratch[SCRATCH_TOTAL];
// fp16 operands
__device__ __align__(16) __half g_xn[NELEM];
__device__ __align__(16) __half g_tn[NELEM];
__device__ __align__(16) __half g_hs[NELEM];
__device__ __align__(16) __half g_qh[NELEM];   // head layout [b,h,n,dh], pre-scaled by 1/8
__device__ __align__(16) __half g_kh[NELEM];
__device__ __align__(16) __half g_vh[NELEM];
__device__ __align__(16) __half g_wt[4 * (size_t)DD * DD];   // transposed weights [n][k]

// ---------------- helpers ----------------
__device__ __forceinline__ uint32_t h2_u32(__half2 h) {
    uint32_t u;
    memcpy(&u, &h, 4);
    return u;
}

// fp16 m16n8k16
__device__ __forceinline__ void mma16(float* c, const uint32_t* a, const uint32_t* b) {
    asm volatile(
        "mma.sync.aligned.m16n8k16.row.col.f32.f16.f16.f32 "
        "{%0,%1,%2,%3},{%4,%5,%6,%7},{%8,%9},{%0,%1,%2,%3};\n"
        : "+f"(c[0]), "+f"(c[1]), "+f"(c[2]), "+f"(c[3])
        : "r"(a[0]), "r"(a[1]), "r"(a[2]), "r"(a[3]), "r"(b[0]), "r"(b[1]));
}

// ldmatrix x4 (b16), non-transposed and transposed
__device__ __forceinline__ void ldsm4(uint32_t& r0, uint32_t& r1, uint32_t& r2, uint32_t& r3,
                                      uint32_t addr) {
    asm volatile("ldmatrix.sync.aligned.m8n8.x4.shared.b16 {%0,%1,%2,%3}, [%4];"
                 : "=r"(r0), "=r"(r1), "=r"(r2), "=r"(r3) : "r"(addr));
}
__device__ __forceinline__ void ldsm4t(uint32_t& r0, uint32_t& r1, uint32_t& r2, uint32_t& r3,
                                       uint32_t addr) {
    asm volatile("ldmatrix.sync.aligned.m8n8.x4.trans.shared.b16 {%0,%1,%2,%3}, [%4];"
                 : "=r"(r0), "=r"(r1), "=r"(r2), "=r"(r3) : "r"(addr));
}

__device__ __forceinline__ uint32_t smem_u32(const void* p) {
    uint32_t a;
    asm("{ .reg .u64 t; cvta.to.shared.u64 t, %1; cvt.u32.u64 %0, t; }" : "=r"(a) : "l"(p));
    return a;
}
__device__ __forceinline__ void cp16(uint32_t d, const void* s) {
    asm volatile("cp.async.cg.shared.global [%0], [%1], 16;\n" :: "r"(d), "l"(s));
}
__device__ __forceinline__ void cp_commit() {
    asm volatile("cp.async.commit_group;\n" ::: "memory");
}
__device__ __forceinline__ void cp_wait0() {
    asm volatile("cp.async.wait_group 0;\n" ::: "memory");
}

// ================= 4-in-1 weight transpose + fp16 convert =================
__global__ void wtrans4_kernel(const float* __restrict__ W0, const float* __restrict__ W1,
                               const float* __restrict__ W2, const float* __restrict__ W3) {
    __shared__ float t[32][33];
    int wi = blockIdx.z;
    const float* W = (wi == 0) ? W0 : (wi == 1) ? W1 : (wi == 2) ? W2 : W3;
    __half* Wt = g_wt + (size_t)wi * DD * DD;
    int nb = blockIdx.x * 32, kb = blockIdx.y * 32;
    int tx = threadIdx.x, ty = threadIdx.y;   // 32 x 8
    #pragma unroll
    for (int i = ty; i < 32; i += 8)
        t[i][tx] = W[(size_t)(kb + i) * DD + nb + tx];
    __syncthreads();
    #pragma unroll
    for (int i = ty; i < 32; i += 8)
        Wt[(size_t)(nb + i) * DD + kb + tx] = __float2half_rn(t[tx][i]);
}

// ================= fused LayerNorm -> fp16 (xn from xa, tn from xb) =================
__global__ void ln2_kernel(const float* __restrict__ x1, const float* __restrict__ x2,
                           const float* __restrict__ gx, const float* __restrict__ bx,
                           const float* __restrict__ gt, const float* __restrict__ bt) {
    int r = blockIdx.x;                // 0..NTOK/2-1
    int tid = threadIdx.x;             // 128 threads, 4 floats each
    float4 v1 = ((const float4*)(x1 + (size_t)r*DD))[tid];
    float4 v2 = ((const float4*)(x2 + (size_t)r*DD))[tid];

    float s1 = v1.x+v1.y+v1.z+v1.w, q1 = v1.x*v1.x+v1.y*v1.y+v1.z*v1.z+v1.w*v1.w;
    float s2 = v2.x+v2.y+v2.z+v2.w, q2 = v2.x*v2.x+v2.y*v2.y+v2.z*v2.z+v2.w*v2.w;

    __shared__ float red[4][4];
    #pragma unroll
    for (int o = 16; o; o >>= 1) {
        s1 += __shfl_xor_sync(0xffffffffu, s1, o);
        q1 += __shfl_xor_sync(0xffffffffu, q1, o);
        s2 += __shfl_xor_sync(0xffffffffu, s2, o);
        q2 += __shfl_xor_sync(0xffffffffu, q2, o);
    }
    if ((tid & 31) == 0) {
        int w = tid >> 5;
        red[0][w] = s1; red[1][w] = q1; red[2][w] = s2; red[3][w] = q2;
    }
    __syncthreads();
    s1 = red[0][0]+red[0][1]+red[0][2]+red[0][3];
    q1 = red[1][0]+red[1][1]+red[1][2]+red[1][3];
    s2 = red[2][0]+red[2][1]+red[2][2]+red[2][3];
    q2 = red[3][0]+red[3][1]+red[3][2]+red[3][3];
    float m1 = s1*(1.0f/DD), iv1 = rsqrtf(q1*(1.0f/DD) - m1*m1 + 1e-5f);
    float m2 = s2*(1.0f/DD), iv2 = rsqrtf(q2*(1.0f/DD) - m2*m2 + 1e-5f);

    float4 ggx = ((const float4*)gx)[tid], bbx = ((const float4*)bx)[tid];
    float4 ggt = ((const float4*)gt)[tid], bbt = ((const float4*)bt)[tid];

    float n1[4] = {(v1.x-m1)*iv1, (v1.y-m1)*iv1, (v1.z-m1)*iv1, (v1.w-m1)*iv1};
    float n2[4] = {(v2.x-m2)*iv2, (v2.y-m2)*iv2, (v2.z-m2)*iv2, (v2.w-m2)*iv2};
    const float* gxp = &ggx.x; const float* bxp = &bbx.x;
    const float* gtp = &ggt.x; const float* btp = &bbt.x;

    const int half_tok = NTOK/2;

    #pragma unroll
    for (int variant = 0; variant < 4; variant++) {
        const float* nv = (variant == 0 || variant == 3) ? n1 : n2;
        const float* gp = (variant < 2) ? gxp : gtp;
        const float* bp = (variant < 2) ? bxp : btp;
        __half* base = (variant < 2) ? g_xn : g_tn;
        int row = (variant == 0 || variant == 2) ? r : r + half_tok;
        float o0 = nv[0]*gp[0] + bp[0];
        float o1 = nv[1]*gp[1] + bp[1];
        float o2 = nv[2]*gp[2] + bp[2];
        float o3 = nv[3]*gp[3] + bp[3];
        __half2* d2 = (__half2*)(base + (size_t)row*DD);
        d2[2*tid]   = __floats2half2_rn(o0, o1);
        d2[2*tid+1] = __floats2half2_rn(o2, o3);
    }
}

// ================= 2-stage pipelined fp16 MMA GEMM, BK=64 =================
#define HROW 72            /* halves per smem row */
#define WROW 36            /* words per smem row */
#define STG_H (128*HROW)   /* halves per stage per matrix: 9216 */
template<bool QKV>
__global__ void __launch_bounds__(256)
mma_gemm(const float* __restrict__ b0p, const float* __restrict__ b1p,
         const float* __restrict__ b2p,
         const float* __restrict__ x1, const float* __restrict__ x2,
         float* __restrict__ outp) {
    extern __shared__ __half hsm[];
    __half* As = hsm;                 // 2 stages x 9216 halves
    __half* Bs = hsm + 2*STG_H;
    uint32_t a_base = smem_u32(As), b_base = smem_u32(Bs);

    int n0g = blockIdx.x * 128;
    int widx, n0;
    const __half *A, *Wt;
    const float* bias;
    __half* Ch = nullptr;
    if (QKV) {
        widx = n0g >> 9;
        n0 = n0g & 511;
        A = (widx == 0) ? g_xn : g_tn;
        Wt = g_wt + (size_t)widx * DD * DD + (size_t)n0 * DD;
        bias = (widx == 0) ? b0p : (widx == 1) ? b1p : b2p;
        Ch = (widx == 0) ? g_qh : (widx == 1) ? g_kh : g_vh;
    } else {
        widx = 3;
        n0 = n0g;
        A = g_hs;
        Wt = g_wt + (size_t)3 * DD * DD + (size_t)n0 * DD;
        bias = b0p;
    }

    int tid = threadIdx.x, lane = tid & 31, wid = tid >> 5;
    int wm = wid >> 2, wn = wid & 3;
    int gid = lane >> 2, tig = lane & 3;
    int m0 = blockIdx.y * 128;
    float c[4][4][4] = {};

    int lrow = tid >> 1, lh = (tid & 1) * 32;   // each thread: one 32-half half-row

    // prologue: stage 0 (k 0..63)
    #pragma unroll
    for (int j = 0; j < 4; j++) {
        uint32_t so = (uint32_t)(lrow*HROW + lh + j*8)*2;
        cp16(a_base + so, A  + (size_t)(m0+lrow)*DD + lh + j*8);
        cp16(b_base + so, Wt + (size_t)lrow*DD      + lh + j*8);
    }
    cp_commit();

    for (int it = 0; it < 8; it++) {
        cp_wait0();        // tile it resident
        __syncthreads();   // all warps past compute(it-1); safe to overwrite other stage

        if (it < 7) {
            int so_st = ((it + 1) & 1) * STG_H;
            int k0 = (it + 1) * 64;
            #pragma unroll
            for (int j = 0; j < 4; j++) {
                uint32_t so = (uint32_t)(so_st + lrow*HROW + lh + j*8)*2;
                cp16(a_base + so, A  + (size_t)(m0+lrow)*DD + k0 + lh + j*8);
                cp16(b_base + so, Wt + (size_t)lrow*DD      + k0 + lh + j*8);
            }
            cp_commit();
        }

        int stw = (it & 1) * (STG_H/2);     // stage offset in words
        const uint32_t* Au = (const uint32_t*)As + stw;
        const uint32_t* Bu = (const uint32_t*)Bs + stw;
        #pragma unroll
        for (int ks = 0; ks < 4; ks++) {
            int c0w = ks*8 + tig;
            int c1w = c0w + 4;
            uint32_t a[4][4];
            #pragma unroll
            for (int mi = 0; mi < 4; mi++) {
                int rm = (wm*64 + mi*16 + gid) * WROW;
                a[mi][0] = Au[rm + c0w];
                a[mi][1] = Au[rm + 8*WROW + c0w];
                a[mi][2] = Au[rm + c1w];
                a[mi][3] = Au[rm + 8*WROW + c1w];
            }
            uint32_t b[4][2];
            #pragma unroll
            for (int ni = 0; ni < 4; ni++) {
                int rn = (wn*32 + ni*8 + gid) * WROW;
                b[ni][0] = Bu[rn + c0w];
                b[ni][1] = Bu[rn + c1w];
            }
            #pragma unroll
            for (int mi = 0; mi < 4; mi++)
                #pragma unroll
                for (int ni = 0; ni < 4; ni++)
                    mma16(c[mi][ni], a[mi], b[ni]);
        }
    }

    float qscale = (QKV && widx == 0) ? 0.125f : 1.0f;
    #pragma unroll
    for (int mi = 0; mi < 4; mi++) {
        #pragma unroll
        for (int ni = 0; ni < 4; ni++) {
            int mA_ = m0 + wm*64 + mi*16 + gid;
            int n  = n0 + wn*32 + ni*8 + 2*tig;
            float v0 = c[mi][ni][0] + bias[n];
            float v1 = c[mi][ni][1] + bias[n+1];
            float v2 = c[mi][ni][2] + bias[n];
            float v3 = c[mi][ni][3] + bias[n+1];
            if (QKV) {
                int h = n >> 6, d = n & 63;
                #pragma unroll
                for (int rr = 0; rr < 2; rr++) {
                    int m = mA_ + rr*8;
                    int b_ = m >> 9, nn = m & 511;
                    __half2* dst = (__half2*)(Ch + (((size_t)(b_*H + h)*T + nn)*DH) + d);
                    *dst = __floats2half2_rn((rr ? v2 : v0) * qscale, (rr ? v3 : v1) * qscale);
                }
            } else {
                #pragma unroll
                for (int rr = 0; rr < 2; rr++) {
                    int m = mA_ + rr*8;
                    const float* src = (m < NTOK/2) ? x1 + (size_t)m*DD
                                                    : x2 + (size_t)(m - NTOK/2)*DD;
                    float2 o;
                    o.x = (rr ? v2 : v0) + src[n];
                    o.y = (rr ? v3 : v1) + src[n+1];
                    *(float2*)(outp + (size_t)m*DD + n) = o;
                }
            }
        }
    }
}

// ================= fused flash attention (exp2 domain, inline fp32 mask) =================
// Q pre-scaled by 1/8; fragments in registers; K,V via ldmatrix; cp.async double buffer.
// Block = 64 q-rows of one (b,h). 4 warps x 16 rows.
// smem (halves, rows padded to 72): 2 x (sK + sV) = 36,864 bytes
#define FHROW 72
__global__ void __launch_bounds__(128)
fa_kernel(const float* __restrict__ mask) {
    extern __shared__ __half fsm[];
    __half* sKb[2] = {fsm,              fsm + 2*64*FHROW};
    __half* sVb[2] = {fsm + 64*FHROW,   fsm + 3*64*FHROW};

    int bh = blockIdx.y, b = bh >> 3, h = bh & 7;
    int n0 = blockIdx.x * 64;
    const __half* Q = g_qh + (size_t)bh*T*DH;
    const __half* K = g_kh + (size_t)bh*T*DH;
    const __half* V = g_vh + (size_t)bh*T*DH;

    int tid = threadIdx.x, lane = tid & 31, w = tid >> 5;
    int gid = lane >> 2, tig = lane & 3;
    int w16 = w * 16;
    int rA = w16 + gid, rB = rA + 8;

    const float* mrowA = mask + ((size_t)b*T + n0 + rA)*T;
    const float* mrowB = mask + ((size_t)b*T + n0 + rB)*T;

    int lrow = tid >> 1, lh = (tid & 1) * 32;

    // ldmatrix lane addressing
    int lg = lane >> 3, lr8 = lane & 7;
    uint32_t vlane_off = (uint32_t)(((lg & 1)*8 + lr8) * FHROW + (lg >> 1) * 8) * 2;
    uint32_t klane_off = (uint32_t)(((lg >> 1)*8 + lr8) * FHROW + (lg & 1) * 8) * 2;

    // Q fragments straight from global into registers (one-time)
    uint32_t aq[4][4];
    #pragma unroll
    for (int ks = 0; ks < 4; ks++) {
        int k0 = ks*16 + 2*tig;
        aq[ks][0] = *(const uint32_t*)(Q + (size_t)(n0+rA)*DH + k0);
        aq[ks][1] = *(const uint32_t*)(Q + (size_t)(n0+rB)*DH + k0);
        aq[ks][2] = *(const uint32_t*)(Q + (size_t)(n0+rA)*DH + k0 + 8);
        aq[ks][3] = *(const uint32_t*)(Q + (size_t)(n0+rB)*DH + k0 + 8);
    }

    // prefetch K/V tile 0 into buffer 0
    {
        uint32_t kb = smem_u32(sKb[0]), vb = smem_u32(sVb[0]);
        #pragma unroll
        for (int j = 0; j < 4; j++) {
            uint32_t so = (uint32_t)(lrow*FHROW + lh + j*8)*2;
            cp16(kb + so, K + (size_t)lrow*DH + lh + j*8);
            cp16(vb + so, V + (size_t)lrow*DH + lh + j*8);
        }
        cp_commit();
    }

    float co[8][4] = {};
    float miA = -1e30f, miB = -1e30f;
    float lA = 0.0f, lB = 0.0f;

    for (int mt = 0; mt < T/64; mt++) {
        int bi = mt & 1;
        cp_wait0();
        __syncthreads();

        if (mt + 1 < T/64) {
            int m1 = (mt + 1) * 64;
            uint32_t kb = smem_u32(sKb[bi ^ 1]), vb = smem_u32(sVb[bi ^ 1]);
            #pragma unroll
            for (int j = 0; j < 4; j++) {
                uint32_t so = (uint32_t)(lrow*FHROW + lh + j*8)*2;
                cp16(kb + so, K + (size_t)(m1+lrow)*DH + lh + j*8);
                cp16(vb + so, V + (size_t)(m1+lrow)*DH + lh + j*8);
            }
            cp_commit();
        }

        int m0 = mt * 64;
        uint32_t kbase = smem_u32(sKb[bi]);
        uint32_t vbase = smem_u32(sVb[bi]);

        // S = Q @ K^T ; K fragments via ldmatrix.x4
        float cs[8][4] = {};
        #pragma unroll
        for (int ks = 0; ks < 4; ks++) {
            uint32_t kcol = kbase + (uint32_t)(ks*16)*2 + klane_off;
            #pragma unroll
            for (int nip = 0; nip < 4; nip++) {
                uint32_t addr = kcol + (uint32_t)(nip*16*FHROW)*2;
                uint32_t b0, b1, b2, b3;
                ldsm4(b0, b1, b2, b3, addr);
                uint32_t bb0[2] = {b0, b1};
                uint32_t bb1[2] = {b2, b3};
                mma16(cs[2*nip],   aq[ks], bb0);
                mma16(cs[2*nip+1], aq[ks], bb1);
            }
        }

        // log2-domain scores + inline mask bias; row max
        float rmA = -1e30f, rmB = -1e30f;
        #pragma unroll
        for (int ni = 0; ni < 8; ni++) {
            int col = ni*8 + 2*tig;
            float2 mA = *(const float2*)(mrowA + m0 + col);
            float2 mB = *(const float2*)(mrowB + m0 + col);
            cs[ni][0] = cs[ni][0]*LOG2E + (1.0f - mA.x)*MBIAS;
            cs[ni][1] = cs[ni][1]*LOG2E + (1.0f - mA.y)*MBIAS;
            cs[ni][2] = cs[ni][2]*LOG2E + (1.0f - mB.x)*MBIAS;
            cs[ni][3] = cs[ni][3]*LOG2E + (1.0f - mB.y)*MBIAS;
            rmA = fmaxf(rmA, fmaxf(cs[ni][0], cs[ni][1]));
            rmB = fmaxf(rmB, fmaxf(cs[ni][2], cs[ni][3]));
        }
        rmA = fmaxf(rmA, __shfl_xor_sync(0xffffffffu, rmA, 1));
        rmA = fmaxf(rmA, __shfl_xor_sync(0xffffffffu, rmA, 2));
        rmB = fmaxf(rmB, __shfl_xor_sync(0xffffffffu, rmB, 1));
        rmB = fmaxf(rmB, __shfl_xor_sync(0xffffffffu, rmB, 2));

        float mnA = fmaxf(miA, rmA), mnB = fmaxf(miB, rmB);
        float alA = exp2f(miA - mnA), alB = exp2f(miB - mnB);
        miA = mnA; miB = mnB;

        // exp2 -> P packed directly as fp16 A-fragments (register resident)
        uint32_t ph[8][2];
        float sumA = 0.0f, sumB = 0.0f;
        #pragma unroll
        for (int ni = 0; ni < 8; ni++) {
            float p0 = exp2f(cs[ni][0] - mnA);
            float p1 = exp2f(cs[ni][1] - mnA);
            float p2 = exp2f(cs[ni][2] - mnB);
            float p3 = exp2f(cs[ni][3] - mnB);
            sumA += p0 + p1; sumB += p2 + p3;
            ph[ni][0] = h2_u32(__floats2half2_rn(p0, p1));
            ph[ni][1] = h2_u32(__floats2half2_rn(p2, p3));
        }
        sumA += __shfl_xor_sync(0xffffffffu, sumA, 1);
        sumA += __shfl_xor_sync(0xffffffffu, sumA, 2);
        sumB += __shfl_xor_sync(0xffffffffu, sumB, 1);
        sumB += __shfl_xor_sync(0xffffffffu, sumB, 2);
        lA = lA * alA + sumA;
        lB = lB * alB + sumB;

        #pragma unroll
        for (int ni = 0; ni < 8; ni++) {
            co[ni][0] *= alA; co[ni][1] *= alA;
            co[ni][2] *= alB; co[ni][3] *= alB;
        }

        // O += P @ V   (A = ph regs; B = V via ldmatrix.x4.trans)
        #pragma unroll
        for (int ks = 0; ks < 4; ks++) {
            uint32_t a[4];
            a[0] = ph[2*ks][0];
            a[1] = ph[2*ks][1];
            a[2] = ph[2*ks+1][0];
            a[3] = ph[2*ks+1][1];
            uint32_t krow_off = vbase + (uint32_t)(ks*16*FHROW)*2 + vlane_off;
            #pragma unroll
            for (int nip = 0; nip < 4; nip++) {
                uint32_t addr = krow_off + (uint32_t)(nip*16)*2;
                uint32_t b0, b1, b2, b3;
                ldsm4t(b0, b1, b2, b3, addr);
                uint32_t bb0[2] = {b0, b1};
                uint32_t bb1[2] = {b2, b3};
                mma16(co[2*nip],   a, bb0);
                mma16(co[2*nip+1], a, bb1);
            }
        }
    }

    // epilogue: normalize + write Y[b,n,D] fp32
    float invA = 1.0f / lA, invB = 1.0f / lB;
    float* Y = g_scratch + OFF_Y;
    int nA = n0 + rA, nB = n0 + rB;
    #pragma unroll
    for (int ni = 0; ni < 8; ni++) {
        int dcol = h*DH + ni*8 + 2*tig;
        float2 oa; oa.x = co[ni][0]*invA; oa.y = co[ni][1]*invA;
        float2 ob; ob.x = co[ni][2]*invB; ob.y = co[ni][3]*invB;
        *(float2*)(Y + ((size_t)(b*T + nA))*DD + dcol) = oa;
        *(float2*)(Y + ((size_t)(b*T + nB))*DD + dcol) = ob;
    }
}

// ================= emb FiLM GEMM, split-K 64 phase 1 =================
__global__ void __launch_bounds__(256)
emb2_kernel(const float* __restrict__ emb, const float* __restrict__ Wemb) {
    __shared__ float se[32 * 33];
    int col0 = blockIdx.x * 64, k0 = blockIdx.y * 32;
    int tid = threadIdx.x;
    for (int i = tid; i < 32 * 32; i += 256) {
        int b = i >> 5, kk = i & 31;
        float e = emb[(size_t)b * TE + k0 + kk];
        se[b * 33 + kk] = e / (1.0f + __expf(-e));
    }
    __syncthreads();

    int col = col0 + (tid & 63);
    int bg = (tid >> 6) << 3;          // 0,8,16,24
    float acc[8] = {};
    #pragma unroll
    for (int kk = 0; kk < 32; kk++) {
        float wv = Wemb[(size_t)(k0 + kk) * (2 * DD) + col];
        #pragma unroll
        for (int j = 0; j < 8; j++)
            acc[j] += se[(bg + j) * 33 + kk] * wv;
    }
    float* P = g_scratch + OFF_EP + (size_t)blockIdx.y * (B2 * 2 * DD);
    #pragma unroll
    for (int j = 0; j < 8; j++)
        P[(size_t)(bg + j) * (2 * DD) + col] = acc[j];
}

// ================= emb split-K phase 2: reduce 64 partials + bias =================
__global__ void embred_kernel(const float* __restrict__ bemb) {
    int i = blockIdx.x * 256 + threadIdx.x;   // 0 .. 32*1024-1
    float s = bemb[i & (2 * DD - 1)];
    #pragma unroll 16
    for (int ks = 0; ks < 64; ks++)
        s += g_scratch[OFF_EP + (size_t)ks * (B2 * 2 * DD) + i];
    g_scratch[OFF_SS + i] = s;
}

// ================= hs = silu( LN(y)*(1+scale) + shift ) -> fp16 =================
__global__ void film_kernel(const float* __restrict__ sbg, const float* __restrict__ sbb) {
    int r = blockIdx.x;
    int b = r >> 9;
    const float* y = g_scratch + OFF_Y + (size_t)r*DD;
    __half* dst = g_hs + (size_t)r*DD;
    const float* ss = g_scratch + OFF_SS + (size_t)b*(2*DD);

    int tid = threadIdx.x;
    float4 v = ((const float4*)y)[tid];
    float s  = v.x + v.y + v.z + v.w;
    float sq = v.x*v.x + v.y*v.y + v.z*v.z + v.w*v.w;
    __shared__ float red[2][4];
    #pragma unroll
    for (int o = 16; o; o >>= 1) {
        s  += __shfl_xor_sync(0xffffffffu, s,  o);
        sq += __shfl_xor_sync(0xffffffffu, sq, o);
    }
    if ((tid & 31) == 0) { red[0][tid>>5] = s; red[1][tid>>5] = sq; }
    __syncthreads();
    s  = red[0][0] + red[0][1] + red[0][2] + red[0][3];
    sq = red[1][0] + red[1][1] + red[1][2] + red[1][3];
    float mean = s * (1.0f/DD);
    float var  = sq * (1.0f/DD) - mean*mean;
    float inv  = rsqrtf(var + 1e-5f);

    int col = tid * 4;
    float vv[4] = {v.x, v.y, v.z, v.w};
    float o[4];
    #pragma unroll
    for (int cc = 0; cc < 4; cc++) {
        float ln = (vv[cc] - mean) * inv * sbg[col + cc] + sbb[col + cc];
        float hh = ln * (1.0f + ss[col + cc]) + ss[512 + col + cc];
        o[cc] = hh / (1.0f + expf(-hh));
    }
    __half2* d2 = (__half2*)dst;
    d2[2*tid]   = __floats2half2_rn(o[0], o[1]);
    d2[2*tid+1] = __floats2half2_rn(o[2], o[3]);
}

// ================= launch =================
extern "C" void kernel_launch(void* const* d_in, const int* in_sizes, int n_in,
                              void* d_out, int out_size) {
    const float* x1    = (const float*)d_in[0];
    const float* x2    = (const float*)d_in[1];
    const float* emb   = (const float*)d_in[2];
    const float* mask  = (const float*)d_in[3];
    const float* ln_x_g = (const float*)d_in[4];
    const float* ln_x_b = (const float*)d_in[5];
    const float* ln_t_g = (const float*)d_in[6];
    const float* ln_t_b = (const float*)d_in[7];
    const float* Wq = (const float*)d_in[8];
    const float* bq = (const float*)d_in[9];
    const float* Wk = (const float*)d_in[10];
    const float* bk = (const float*)d_in[11];
    const float* Wv = (const float*)d_in[12];
    const float* bv = (const float*)d_in[13];
    const float* Wemb = (const float*)d_in[14];
    const float* bemb = (const float*)d_in[15];
    const float* sb_g = (const float*)d_in[16];
    const float* sb_b = (const float*)d_in[17];
    const float* Wout = (const float*)d_in[18];
    const float* bout = (const float*)d_in[19];
    float* out = (float*)d_out;

    const int gemm_smem = 4 * STG_H * 2;       // 73728 bytes (2 stages x A,B)
    const int fa_smem   = 4 * 64 * FHROW * 2;  // 36864 bytes
    cudaFuncSetAttribute(mma_gemm<true>,  cudaFuncAttributeMaxDynamicSharedMemorySize, gemm_smem);
    cudaFuncSetAttribute(mma_gemm<false>, cudaFuncAttributeMaxDynamicSharedMemorySize, gemm_smem);
    cudaFuncSetAttribute(fa_kernel,       cudaFuncAttributeMaxDynamicSharedMemorySize, fa_smem);

    wtrans4_kernel<<<dim3(16, 16, 4), dim3(32, 8)>>>(Wq, Wk, Wv, Wout);
    ln2_kernel<<<NTOK/2, 128>>>(x1, x2, ln_x_g, ln_x_b, ln_t_g, ln_t_b);
    emb2_kernel<<<dim3(16, 64), 256>>>(emb, Wemb);   // independent; fills profiler slot 3

    // fused Q/K/V projection: N = 1536 (slot 4 -> profiled by ncu)
    mma_gemm<true><<<dim3(12, NTOK/128), 256, gemm_smem>>>(bq, bk, bv, x1, x2, nullptr);

    fa_kernel<<<dim3(T/64, B2*H), 128, fa_smem>>>(mask);

    embred_kernel<<<(B2*2*DD)/256, 256>>>(bemb);
    film_kernel<<<NTOK, 128>>>(sb_g, sb_b);
    mma_gemm<false><<<dim3(4, NTOK/128), 256, gemm_smem>>>(bout, nullptr, nullptr, x1, x2, out);
}